// round 12
// baseline (speedup 1.0000x reference)
#include <cuda_runtime.h>
#include <cuda_bf16.h>

// ActionEncoder: out[b] = tanh(b_t + sum_s W_t[:, s*64 + idx[b,s]])
// R4 layout (2 adjacent samples/thread, int4+int2 coalesced loads) with a
// MUFU-minimized tanh:
//   tables store 2*log2(e)*(W+b)  ->  e^{2x} = ex2(a+c)      (1 MUFU, no FMUL)
//   the 4 denominators (e_i+1) of one sample share ONE MUFU.RCP via the
//   product-reciprocal trick; per-component 1/d recovered with FMULs.
// MUFU per thread: 10 (8 EX2 + 2 RCP) vs 16 before.

#define MAX_N 64

__device__ __forceinline__ float ex2f(float x) {
    float r;
    asm("ex2.approx.f32 %0, %1;" : "=f"(r) : "f"(x));
    return r;
}
__device__ __forceinline__ float rcpf(float x) {
    float r;
    asm("rcp.approx.f32 %0, %1;" : "=f"(r) : "f"(x));
    return r;
}

__device__ __forceinline__ float4 enc(const float4* Ta, const float4* Tb,
                                      int t, int i0, int i1) {
    int off = t << 6;
    float4 a = Ta[off + i0];   // 2*log2e*(slot0 + bias)
    float4 c = Tb[off + i1];   // 2*log2e*slot1 (0 for t=0)
    float e0 = ex2f(a.x + c.x);
    float e1 = ex2f(a.y + c.y);
    float e2 = ex2f(a.z + c.z);
    float e3 = ex2f(a.w + c.w);
    // tanh = (e-1)/(e+1); one RCP serves all 4 components.
    float d0 = e0 + 1.f, d1 = e1 + 1.f, d2 = e2 + 1.f, d3 = e3 + 1.f;
    float p01 = d0 * d1;
    float p23 = d2 * d3;
    float r   = rcpf(p01 * p23);
    float q01 = p23 * r;       // 1/(d0*d1)
    float q23 = p01 * r;       // 1/(d2*d3)
    return make_float4((e0 - 1.f) * (d1 * q01),
                       (e1 - 1.f) * (d0 * q01),
                       (e2 - 1.f) * (d3 * q23),
                       (e3 - 1.f) * (d2 * q23));
}

__global__ __launch_bounds__(256)
void action_encoder_kernel(const int4* __restrict__ idx2,    // [B/2] two (i0,i1) pairs
                           const int2* __restrict__ types2,  // [B/2] two types
                           const float* __restrict__ W0,     // [4,64]
                           const float* __restrict__ b0,     // [4]
                           const float* __restrict__ W1,     // [4,128]
                           const float* __restrict__ b1,     // [4]
                           float4* __restrict__ out,         // [B]
                           int Bpairs) {
    __shared__ float4 Ta[2 * MAX_N];
    __shared__ float4 Tb[2 * MAX_N];
    const float S = 2.8853900817779268f;   // 2*log2(e)
    int tid = threadIdx.x;
    if (tid < MAX_N) {
        Ta[tid] = make_float4(S * (W0[0*64 + tid] + b0[0]),
                              S * (W0[1*64 + tid] + b0[1]),
                              S * (W0[2*64 + tid] + b0[2]),
                              S * (W0[3*64 + tid] + b0[3]));
        Tb[tid] = make_float4(0.f, 0.f, 0.f, 0.f);
    } else if (tid < 2 * MAX_N) {
        int j = tid - MAX_N;
        Ta[tid] = make_float4(S * (W1[0*128 + j] + b1[0]),
                              S * (W1[1*128 + j] + b1[1]),
                              S * (W1[2*128 + j] + b1[2]),
                              S * (W1[3*128 + j] + b1[3]));
        Tb[tid] = make_float4(S * W1[0*128 + 64 + j],
                              S * W1[1*128 + 64 + j],
                              S * W1[2*128 + 64 + j],
                              S * W1[3*128 + 64 + j]);
    }
    __syncthreads();

    int p = blockIdx.x * blockDim.x + tid;   // pair index
    if (p >= Bpairs) return;

    int4 ix = idx2[p];    // one coalesced 16B load: both samples' indices
    int2 tt = types2[p];  // one coalesced  8B load: both types

    float4 r0 = enc(Ta, Tb, tt.x, ix.x, ix.y);
    float4 r1 = enc(Ta, Tb, tt.y, ix.z, ix.w);

    out[2 * p]     = r0;
    out[2 * p + 1] = r1;
}

extern "C" void kernel_launch(void* const* d_in, const int* in_sizes, int n_in,
                              void* d_out, int out_size) {
    // metadata order: action_indecies, action_n_obj, action_types, W0, b0, W1, b1
    const int4*  idx2   = (const int4*) d_in[0];
    const int2*  types2 = (const int2*) d_in[2];
    const float* W0     = (const float*)d_in[3];
    const float* b0     = (const float*)d_in[4];
    const float* W1     = (const float*)d_in[5];
    const float* b1     = (const float*)d_in[6];
    float4* out = (float4*)d_out;

    int B = in_sizes[2];      // 524288 (even)
    int Bpairs = B >> 1;      // 262144

    int threads = 256;
    int blocks  = (Bpairs + threads - 1) / threads;  // 1024
    action_encoder_kernel<<<blocks, threads>>>(idx2, types2, W0, b0, W1, b1,
                                               out, Bpairs);
}

// round 13
// speedup vs baseline: 1.1111x; 1.1111x over previous
#include <cuda_runtime.h>
#include <cuda_bf16.h>

// ActionEncoder: out[b] = tanh(b_t + sum_s W_t[:, s*64 + idx[b,s]])
// Best-measured layout (pairs: 2 adjacent samples/thread, int4+int2 coalesced
// loads) + sm_100a 256-bit store: both float4 results written with ONE STG.256
// (32B-aligned), halving store instrs and L1 store wavefronts.
// Tables store 2*log2e*(W+b) so e^{2x} = ex2(a+c): 1 MUFU.EX2 per component.

#define MAX_N 64

__device__ __forceinline__ float ex2f(float x) {
    float r;
    asm("ex2.approx.f32 %0, %1;" : "=f"(r) : "f"(x));
    return r;
}

__device__ __forceinline__ float4 enc(const float4* Ta, const float4* Tb,
                                      int t, int i0, int i1) {
    int off = t << 6;
    float4 a = Ta[off + i0];   // 2*log2e*(slot0 + bias)
    float4 c = Tb[off + i1];   // 2*log2e*slot1 (0 for t=0)
    float e0 = ex2f(a.x + c.x);
    float e1 = ex2f(a.y + c.y);
    float e2 = ex2f(a.z + c.z);
    float e3 = ex2f(a.w + c.w);
    // tanh = (e-1)/(e+1)
    return make_float4(__fdividef(e0 - 1.f, e0 + 1.f),
                       __fdividef(e1 - 1.f, e1 + 1.f),
                       __fdividef(e2 - 1.f, e2 + 1.f),
                       __fdividef(e3 - 1.f, e3 + 1.f));
}

__global__ __launch_bounds__(256)
void action_encoder_kernel(const int4* __restrict__ idx2,    // [B/2] two (i0,i1) pairs
                           const int2* __restrict__ types2,  // [B/2] two types
                           const float* __restrict__ W0,     // [4,64]
                           const float* __restrict__ b0,     // [4]
                           const float* __restrict__ W1,     // [4,128]
                           const float* __restrict__ b1,     // [4]
                           float4* __restrict__ out,         // [B]
                           int Bpairs) {
    __shared__ float4 Ta[2 * MAX_N];
    __shared__ float4 Tb[2 * MAX_N];
    const float S = 2.8853900817779268f;   // 2*log2(e)
    int tid = threadIdx.x;
    if (tid < MAX_N) {
        Ta[tid] = make_float4(S * (W0[0*64 + tid] + b0[0]),
                              S * (W0[1*64 + tid] + b0[1]),
                              S * (W0[2*64 + tid] + b0[2]),
                              S * (W0[3*64 + tid] + b0[3]));
        Tb[tid] = make_float4(0.f, 0.f, 0.f, 0.f);
    } else if (tid < 2 * MAX_N) {
        int j = tid - MAX_N;
        Ta[tid] = make_float4(S * (W1[0*128 + j] + b1[0]),
                              S * (W1[1*128 + j] + b1[1]),
                              S * (W1[2*128 + j] + b1[2]),
                              S * (W1[3*128 + j] + b1[3]));
        Tb[tid] = make_float4(S * W1[0*128 + 64 + j],
                              S * W1[1*128 + 64 + j],
                              S * W1[2*128 + 64 + j],
                              S * W1[3*128 + 64 + j]);
    }
    __syncthreads();

    int p = blockIdx.x * blockDim.x + tid;   // pair index
    if (p >= Bpairs) return;

    int4 ix = idx2[p];    // one coalesced 16B load: both samples' indices
    int2 tt = types2[p];  // one coalesced  8B load: both types

    float4 r0 = enc(Ta, Tb, tt.x, ix.x, ix.y);
    float4 r1 = enc(Ta, Tb, tt.y, ix.z, ix.w);

    // One 256-bit store for both adjacent float4 results (sm_100a feature).
    // out + 2*p is 32B-aligned (32 bytes * p from a 256B-aligned base).
    float* o = (float*)(out + 2 * p);
    asm volatile("st.global.v8.f32 [%0], {%1,%2,%3,%4,%5,%6,%7,%8};"
                 :: "l"(o),
                    "f"(r0.x), "f"(r0.y), "f"(r0.z), "f"(r0.w),
                    "f"(r1.x), "f"(r1.y), "f"(r1.z), "f"(r1.w)
                 : "memory");
}

extern "C" void kernel_launch(void* const* d_in, const int* in_sizes, int n_in,
                              void* d_out, int out_size) {
    // metadata order: action_indecies, action_n_obj, action_types, W0, b0, W1, b1
    const int4*  idx2   = (const int4*) d_in[0];
    const int2*  types2 = (const int2*) d_in[2];
    const float* W0     = (const float*)d_in[3];
    const float* b0     = (const float*)d_in[4];
    const float* W1     = (const float*)d_in[5];
    const float* b1     = (const float*)d_in[6];
    float4* out = (float4*)d_out;

    int B = in_sizes[2];      // 524288 (even)
    int Bpairs = B >> 1;      // 262144

    int threads = 256;
    int blocks  = (Bpairs + threads - 1) / threads;  // 1024
    action_encoder_kernel<<<blocks, threads>>>(idx2, types2, W0, b0, W1, b1,
                                               out, Bpairs);
}